// round 6
// baseline (speedup 1.0000x reference)
#include <cuda_runtime.h>
#include <cuda_bf16.h>

// embeddings [B=512, I=128, D=64] fp32
// out[b,i,d] = tanh( emb[b,i,d] * (1/I) * sum_j emb[b,j,d] )
//
// R6: cross-batch software pipeline. Each CTA handles the SAME 8-f4-column
// chunk of TWO batches. All 8 LDG.128 issued up front (both batches in
// flight), the two reduce/final chains interleave and the final 8-partial
// reductions run in parallel thread groups (t<8: b0, 8<=t<16: b1) under
// shared barriers. Grid 512 x 256 thr. Traffic = 33.5 MB floor.

static constexpr int BATCH   = 512;
static constexpr int SEQ_I   = 128;
static constexpr int F4_ROW  = 16;      // 64 floats / 4
static constexpr int F4_COLS = 8;       // f4 columns per CTA chunk
static constexpr int THREADS = 256;

__device__ __forceinline__ float fast_tanh(float x) {
    float y;
    asm("tanh.approx.f32 %0, %1;" : "=f"(y) : "f"(x));
    return y;
}

__device__ __forceinline__ float4 warp_col_reduce(float4 s) {
#pragma unroll
    for (int off = 8; off <= 16; off <<= 1) {
        s.x += __shfl_xor_sync(0xffffffffu, s.x, off);
        s.y += __shfl_xor_sync(0xffffffffu, s.y, off);
        s.z += __shfl_xor_sync(0xffffffffu, s.z, off);
        s.w += __shfl_xor_sync(0xffffffffu, s.w, off);
    }
    return s;
}

__global__ __launch_bounds__(THREADS, 4)
void ATT0_40707700032104_kernel(const float4* __restrict__ in,
                                float4* __restrict__ out) {
    const int pair = blockIdx.x >> 1;     // batch pair (0..255)
    const int half = blockIdx.x & 1;      // which 8-f4-column chunk
    const int b0   = pair * 2;
    const int b1   = b0 + 1;
    const int t    = threadIdx.x;
    const int c    = t & (F4_COLS - 1);   // f4 column in chunk (0..7)
    const int rg   = t >> 3;              // base row (0..31)
    const int lane = t & 31;
    const int w    = t >> 5;              // warp id (0..7)

    const size_t off  = (size_t)half * F4_COLS + c;
    const size_t bs0  = (size_t)b0 * (SEQ_I * F4_ROW) + off;
    const size_t bs1  = (size_t)b1 * (SEQ_I * F4_ROW) + off;
    const float4* src0 = in + bs0;
    const float4* src1 = in + bs1;
    float4* dst0 = out + bs0;
    float4* dst1 = out + bs1;

    // ---- Issue ALL 8 independent LDG.128 up front (both batches) ----
    float4 v0[4], v1[4];
#pragma unroll
    for (int k = 0; k < 4; k++) v0[k] = src0[(size_t)(rg + 32 * k) * F4_ROW];
#pragma unroll
    for (int k = 0; k < 4; k++) v1[k] = src1[(size_t)(rg + 32 * k) * F4_ROW];

    // ---- Per-thread column partials ----
    float4 s0, s1;
    s0.x = (v0[0].x + v0[1].x) + (v0[2].x + v0[3].x);
    s0.y = (v0[0].y + v0[1].y) + (v0[2].y + v0[3].y);
    s0.z = (v0[0].z + v0[1].z) + (v0[2].z + v0[3].z);
    s0.w = (v0[0].w + v0[1].w) + (v0[2].w + v0[3].w);
    s1.x = (v1[0].x + v1[1].x) + (v1[2].x + v1[3].x);
    s1.y = (v1[0].y + v1[1].y) + (v1[2].y + v1[3].y);
    s1.z = (v1[0].z + v1[1].z) + (v1[2].z + v1[3].z);
    s1.w = (v1[0].w + v1[1].w) + (v1[2].w + v1[3].w);

    // ---- Warp reduce both batches ----
    s0 = warp_col_reduce(s0);
    s1 = warp_col_reduce(s1);

    // ---- Publish per-warp column sums for both batches; one barrier ----
    __shared__ float4 wsum[2][8][F4_COLS];
    __shared__ float4 mean4[2][F4_COLS];
    if (lane < F4_COLS) {
        wsum[0][w][lane] = s0;
        wsum[1][w][lane] = s1;
    }
    __syncthreads();

    // ---- Parallel final reductions: t<8 -> batch0, 8<=t<16 -> batch1 ----
    if (t < 16) {
        const int g  = t >> 3;            // 0: batch0, 1: batch1
        const int cc = t & 7;
        float4 m = wsum[g][0][cc];
#pragma unroll
        for (int ww = 1; ww < 8; ww++) {
            float4 p = wsum[g][ww][cc];
            m.x += p.x; m.y += p.y; m.z += p.z; m.w += p.w;
        }
        const float inv = 1.0f / (float)SEQ_I;
        m.x *= inv; m.y *= inv; m.z *= inv; m.w *= inv;
        mean4[g][cc] = m;
    }
    __syncthreads();

    const float4 m0 = mean4[0][c];
    const float4 m1 = mean4[1][c];

    // ---- tanh(v * mean) from registers, 8 coalesced STG.128 ----
#pragma unroll
    for (int k = 0; k < 4; k++) {
        float4 r;
        r.x = fast_tanh(v0[k].x * m0.x);
        r.y = fast_tanh(v0[k].y * m0.y);
        r.z = fast_tanh(v0[k].z * m0.z);
        r.w = fast_tanh(v0[k].w * m0.w);
        dst0[(size_t)(rg + 32 * k) * F4_ROW] = r;
    }
#pragma unroll
    for (int k = 0; k < 4; k++) {
        float4 r;
        r.x = fast_tanh(v1[k].x * m1.x);
        r.y = fast_tanh(v1[k].y * m1.y);
        r.z = fast_tanh(v1[k].z * m1.z);
        r.w = fast_tanh(v1[k].w * m1.w);
        dst1[(size_t)(rg + 32 * k) * F4_ROW] = r;
    }
}

extern "C" void kernel_launch(void* const* d_in, const int* in_sizes, int n_in,
                              void* d_out, int out_size) {
    const float4* in  = (const float4*)d_in[0];
    float4*       out = (float4*)d_out;
    ATT0_40707700032104_kernel<<<BATCH, THREADS>>>(in, out);
}